// round 2
// baseline (speedup 1.0000x reference)
#include <cuda_runtime.h>
#include <math.h>

// ----------------------------------------------------------------------------
// Problem constants
// ----------------------------------------------------------------------------
#define B_   2
#define L_   2048
#define DIM_ 1024
#define H_   16
#define D_   64
#define BL_  (B_ * L_)         // 4096
#define BH_  (B_ * H_)         // 32

// Scratch (device globals — allocation-free per harness rules)
__device__ float g_qkv[BL_ * 3 * DIM_];                // [4096, 3072]
__device__ float g_q[BH_ * L_ * D_];                   // [B,H,L,D]
__device__ float g_k[BH_ * L_ * D_];
__device__ float g_v[BH_ * L_ * D_];
__device__ float g_o[BL_ * DIM_];                      // [B,L,H,D] == [B,L,DIM]

// ----------------------------------------------------------------------------
// SGEMM: C[M,N] = A[M,K] @ B[K,N] (+ bias[N]), row-major, tiles 128x128x16
// ----------------------------------------------------------------------------
__global__ __launch_bounds__(256) void sgemm128(
    const float* __restrict__ A, const float* __restrict__ Bm,
    const float* __restrict__ bias, float* __restrict__ C,
    int M, int N, int K)
{
    __shared__ float As[16][128];   // [k][m]
    __shared__ float Bs[16][128];   // [k][n]

    const int tid = threadIdx.x;
    const int tx = tid & 15;
    const int ty = tid >> 4;
    const int row0 = blockIdx.y * 128;
    const int col0 = blockIdx.x * 128;

    float acc[8][8];
#pragma unroll
    for (int i = 0; i < 8; i++)
#pragma unroll
        for (int j = 0; j < 8; j++) acc[i][j] = 0.f;

    for (int k0 = 0; k0 < K; k0 += 16) {
        // Load A tile (128x16), store transposed
#pragma unroll
        for (int it = 0; it < 2; it++) {
            int idx = tid + it * 256;       // 0..511
            int r = idx >> 2;               // 0..127
            int kq = idx & 3;               // 0..3
            float4 a = *(const float4*)(A + (size_t)(row0 + r) * K + k0 + kq * 4);
            As[kq * 4 + 0][r] = a.x;
            As[kq * 4 + 1][r] = a.y;
            As[kq * 4 + 2][r] = a.z;
            As[kq * 4 + 3][r] = a.w;
        }
        // Load B tile (16x128)
#pragma unroll
        for (int it = 0; it < 2; it++) {
            int idx = tid + it * 256;
            int kr = idx >> 5;              // 0..15
            int cq = idx & 31;              // 0..31
            *(float4*)(&Bs[kr][cq * 4]) =
                *(const float4*)(Bm + (size_t)(k0 + kr) * N + col0 + cq * 4);
        }
        __syncthreads();

#pragma unroll
        for (int k = 0; k < 16; k++) {
            float a[8], b[8];
            *(float4*)(a)     = *(float4*)(&As[k][ty * 8]);
            *(float4*)(a + 4) = *(float4*)(&As[k][ty * 8 + 4]);
            *(float4*)(b)     = *(float4*)(&Bs[k][tx * 8]);
            *(float4*)(b + 4) = *(float4*)(&Bs[k][tx * 8 + 4]);
#pragma unroll
            for (int i = 0; i < 8; i++)
#pragma unroll
                for (int j = 0; j < 8; j++) acc[i][j] += a[i] * b[j];
        }
        __syncthreads();
    }

#pragma unroll
    for (int i = 0; i < 8; i++) {
        int r = row0 + ty * 8 + i;
#pragma unroll
        for (int j = 0; j < 8; j += 4) {
            int c = col0 + tx * 8 + j;
            float4 v;
            v.x = acc[i][j + 0];
            v.y = acc[i][j + 1];
            v.z = acc[i][j + 2];
            v.w = acc[i][j + 3];
            if (bias) {
                v.x += bias[c + 0];
                v.y += bias[c + 1];
                v.z += bias[c + 2];
                v.w += bias[c + 3];
            }
            *(float4*)(C + (size_t)r * N + c) = v;
        }
    }
}

// ----------------------------------------------------------------------------
// RMSNorm (over D=64) + RoPE; split qkv into q/k/v in [B,H,L,D].
// One warp per (b,h,l): lane handles d = 2*lane, 2*lane+1 (a RoPE pair).
// ----------------------------------------------------------------------------
__global__ __launch_bounds__(256) void rmsrope_kernel(
    const float* __restrict__ qkv, const float* __restrict__ pe,
    const float* __restrict__ qscale, const float* __restrict__ kscale,
    float* __restrict__ q, float* __restrict__ k, float* __restrict__ v)
{
    const int warp = (blockIdx.x * blockDim.x + threadIdx.x) >> 5;  // 0..65535
    const int lane = threadIdx.x & 31;
    const int b = warp >> 15;           // / (H*L)
    const int rem = warp & 32767;
    const int h = rem >> 11;            // / L
    const int l = rem & 2047;

    const float* base = qkv + ((size_t)(b * L_ + l)) * (3 * DIM_) + h * D_;
    float2 q2 = *(const float2*)(base + lane * 2);
    float2 k2 = *(const float2*)(base + DIM_ + lane * 2);
    float2 v2 = *(const float2*)(base + 2 * DIM_ + lane * 2);

    float sq = q2.x * q2.x + q2.y * q2.y;
    float sk = k2.x * k2.x + k2.y * k2.y;
#pragma unroll
    for (int o = 16; o > 0; o >>= 1) {
        sq += __shfl_xor_sync(0xffffffffu, sq, o);
        sk += __shfl_xor_sync(0xffffffffu, sk, o);
    }
    const float qinv = rsqrtf(sq * (1.f / 64.f) + 1e-6f);
    const float kinv = rsqrtf(sk * (1.f / 64.f) + 1e-6f);

    float2 qsc = *(const float2*)(qscale + lane * 2);
    float2 ksc = *(const float2*)(kscale + lane * 2);
    float t0 = q2.x * qinv * qsc.x;
    float t1 = q2.y * qinv * qsc.y;
    float u0 = k2.x * kinv * ksc.x;
    float u1 = k2.y * kinv * ksc.y;

    // pe[b,0,l,j,r,c]; j = lane
    float4 p = *(const float4*)(pe + (((size_t)(b * L_ + l)) * 32 + lane) * 4);
    float2 qo, ko;
    qo.x = p.x * t0 + p.y * t1;   // r=0
    qo.y = p.z * t0 + p.w * t1;   // r=1
    ko.x = p.x * u0 + p.y * u1;
    ko.y = p.z * u0 + p.w * u1;

    const size_t orow = ((size_t)((b * H_ + h) * L_ + l)) * D_;
    *(float2*)(q + orow + lane * 2) = qo;
    *(float2*)(k + orow + lane * 2) = ko;
    *(float2*)(v + orow + lane * 2) = v2;
}

// ----------------------------------------------------------------------------
// Flash attention fp32: 64x64 tiles. Q/K stored d-major in smem so both GEMM
// phases read float4. Online softmax by 64 row-threads on transposed S.
// Writes O directly in [B,L,H,D] layout for the projection GEMM.
// ----------------------------------------------------------------------------
#define APAD 68                       // padded row of 68 floats (16B-aligned)
#define ATTN_SMEM_BYTES ((4 * 64 * APAD + 3 * 64) * 4)

__global__ __launch_bounds__(256) void attn_kernel(
    const float* __restrict__ q, const float* __restrict__ k,
    const float* __restrict__ v, float* __restrict__ o)
{
    extern __shared__ float sm[];
    float* sQt = sm;                    // [d][r]
    float* sKt = sm + 64 * APAD;        // [d][c]
    float* sV  = sm + 2 * 64 * APAD;    // [c][d]
    float* sS  = sm + 3 * 64 * APAD;    // [c][r]  (transposed scores)
    float* rM  = sm + 4 * 64 * APAD;    // [64]
    float* rL  = rM + 64;
    float* rA  = rL + 64;

    const int tid = threadIdx.x;
    const int tx = tid & 15;
    const int ty = tid >> 4;
    const int bh = blockIdx.y;          // 0..31
    const int q0 = blockIdx.x * 64;
    const size_t bhoff = (size_t)bh * L_ * D_;
    const float* Q = q + bhoff;
    const float* K = k + bhoff;
    const float* V = v + bhoff;
    const float scale = 0.125f;         // 1/sqrt(64)

    // Load Q tile, scaled, transposed to [d][r]
#pragma unroll
    for (int it = 0; it < 4; it++) {
        int idx = tid + it * 256;
        int r = idx >> 4;
        int dq = idx & 15;
        float4 a = *(const float4*)(Q + (size_t)(q0 + r) * D_ + dq * 4);
        sQt[(dq * 4 + 0) * APAD + r] = a.x * scale;
        sQt[(dq * 4 + 1) * APAD + r] = a.y * scale;
        sQt[(dq * 4 + 2) * APAD + r] = a.z * scale;
        sQt[(dq * 4 + 3) * APAD + r] = a.w * scale;
    }
    if (tid < 64) { rM[tid] = -INFINITY; rL[tid] = 0.f; }

    float acc[4][4];
#pragma unroll
    for (int i = 0; i < 4; i++)
#pragma unroll
        for (int j = 0; j < 4; j++) acc[i][j] = 0.f;

    __syncthreads();

    for (int c0 = 0; c0 < L_; c0 += 64) {
        // Load K tile transposed, V tile direct
#pragma unroll
        for (int it = 0; it < 4; it++) {
            int idx = tid + it * 256;
            int r = idx >> 4;
            int dq = idx & 15;
            float4 a = *(const float4*)(K + (size_t)(c0 + r) * D_ + dq * 4);
            sKt[(dq * 4 + 0) * APAD + r] = a.x;
            sKt[(dq * 4 + 1) * APAD + r] = a.y;
            sKt[(dq * 4 + 2) * APAD + r] = a.z;
            sKt[(dq * 4 + 3) * APAD + r] = a.w;
            float4 bvec = *(const float4*)(V + (size_t)(c0 + r) * D_ + dq * 4);
            *(float4*)(&sV[r * APAD + dq * 4]) = bvec;
        }
        __syncthreads();

        // S = Q K^T  (4x4 per thread)
        float s[4][4];
#pragma unroll
        for (int i = 0; i < 4; i++)
#pragma unroll
            for (int j = 0; j < 4; j++) s[i][j] = 0.f;
#pragma unroll 8
        for (int d = 0; d < 64; d++) {
            float4 qa = *(float4*)(&sQt[d * APAD + ty * 4]);
            float4 kb = *(float4*)(&sKt[d * APAD + tx * 4]);
            float qv[4] = {qa.x, qa.y, qa.z, qa.w};
            float kv[4] = {kb.x, kb.y, kb.z, kb.w};
#pragma unroll
            for (int i = 0; i < 4; i++)
#pragma unroll
                for (int j = 0; j < 4; j++) s[i][j] += qv[i] * kv[j];
        }
        // Store transposed: sS[c][r]
#pragma unroll
        for (int j = 0; j < 4; j++)
#pragma unroll
            for (int i = 0; i < 4; i++)
                sS[(tx * 4 + j) * APAD + ty * 4 + i] = s[i][j];
        __syncthreads();

        // Online softmax: one thread per query row
        if (tid < 64) {
            const int r = tid;
            float mold = rM[r];
            float mt = mold;
#pragma unroll 8
            for (int c = 0; c < 64; c++) mt = fmaxf(mt, sS[c * APAD + r]);
            float alpha = __expf(mold - mt);
            float sum = 0.f;
#pragma unroll 8
            for (int c = 0; c < 64; c++) {
                float p = __expf(sS[c * APAD + r] - mt);
                sS[c * APAD + r] = p;
                sum += p;
            }
            rM[r] = mt;
            rL[r] = rL[r] * alpha + sum;
            rA[r] = alpha;
        }
        __syncthreads();

        // acc = acc*alpha + P @ V
        float al[4];
#pragma unroll
        for (int i = 0; i < 4; i++) al[i] = rA[ty * 4 + i];
#pragma unroll
        for (int i = 0; i < 4; i++)
#pragma unroll
            for (int j = 0; j < 4; j++) acc[i][j] *= al[i];
#pragma unroll 8
        for (int c = 0; c < 64; c++) {
            float4 pa = *(float4*)(&sS[c * APAD + ty * 4]);
            float4 vb = *(float4*)(&sV[c * APAD + tx * 4]);
            float pv[4] = {pa.x, pa.y, pa.z, pa.w};
            float vv[4] = {vb.x, vb.y, vb.z, vb.w};
#pragma unroll
            for (int i = 0; i < 4; i++)
#pragma unroll
                for (int j = 0; j < 4; j++) acc[i][j] += pv[i] * vv[j];
        }
        __syncthreads();
    }

    // Epilogue: normalize + write [B,L,H,D]
    const int b = bh >> 4;
    const int h = bh & 15;
    float linv[4];
#pragma unroll
    for (int i = 0; i < 4; i++) linv[i] = 1.f / rL[ty * 4 + i];
#pragma unroll
    for (int i = 0; i < 4; i++) {
        int token = q0 + ty * 4 + i;
        float4 ov;
        ov.x = acc[i][0] * linv[i];
        ov.y = acc[i][1] * linv[i];
        ov.z = acc[i][2] * linv[i];
        ov.w = acc[i][3] * linv[i];
        *(float4*)(o + (((size_t)(b * L_ + token)) * H_ + h) * D_ + tx * 4) = ov;
    }
}

// ----------------------------------------------------------------------------
// Launch
// ----------------------------------------------------------------------------
extern "C" void kernel_launch(void* const* d_in, const int* in_sizes, int n_in,
                              void* d_out, int out_size)
{
    const float* x      = (const float*)d_in[0];
    const float* pe     = (const float*)d_in[1];
    const float* w_qkv  = (const float*)d_in[2];
    const float* qscale = (const float*)d_in[3];
    const float* kscale = (const float*)d_in[4];
    const float* w_proj = (const float*)d_in[5];
    const float* b_proj = (const float*)d_in[6];
    float* out = (float*)d_out;

    float *p_qkv, *p_q, *p_k, *p_v, *p_o;
    cudaGetSymbolAddress((void**)&p_qkv, g_qkv);
    cudaGetSymbolAddress((void**)&p_q, g_q);
    cudaGetSymbolAddress((void**)&p_k, g_k);
    cudaGetSymbolAddress((void**)&p_v, g_v);
    cudaGetSymbolAddress((void**)&p_o, g_o);

    cudaFuncSetAttribute(attn_kernel, cudaFuncAttributeMaxDynamicSharedMemorySize,
                         ATTN_SMEM_BYTES);

    // 1. QKV GEMM: [4096,1024] @ [1024,3072]
    {
        dim3 grid(3 * DIM_ / 128, BL_ / 128);
        sgemm128<<<grid, 256>>>(x, w_qkv, nullptr, p_qkv, BL_, 3 * DIM_, DIM_);
    }
    // 2. RMSNorm + RoPE + split
    {
        int warps = B_ * H_ * L_;              // 65536
        rmsrope_kernel<<<warps * 32 / 256, 256>>>(p_qkv, pe, qscale, kscale,
                                                  p_q, p_k, p_v);
    }
    // 3. Attention
    {
        dim3 grid(L_ / 64, BH_);
        attn_kernel<<<grid, 256, ATTN_SMEM_BYTES>>>(p_q, p_k, p_v, p_o);
    }
    // 4. Output projection: [4096,1024] @ [1024,1024] + bias
    {
        dim3 grid(DIM_ / 128, BL_ / 128);
        sgemm128<<<grid, 256>>>(p_o, w_proj, b_proj, out, BL_, DIM_, DIM_);
    }
}

// round 3
// speedup vs baseline: 1.0011x; 1.0011x over previous
#include <cuda_runtime.h>
#include <math.h>

// ----------------------------------------------------------------------------
// Problem constants
// ----------------------------------------------------------------------------
#define B_   2
#define L_   2048
#define DIM_ 1024
#define H_   16
#define D_   64
#define BL_  (B_ * L_)         // 4096
#define BH_  (B_ * H_)         // 32

// Scratch (device globals — allocation-free per harness rules)
__device__ float g_qkv[BL_ * 3 * DIM_];                // [4096, 3072]
__device__ float g_q[BH_ * L_ * D_];                   // [B,H,L,D]
__device__ float g_k[BH_ * L_ * D_];
__device__ float g_v[BH_ * L_ * D_];
__device__ float g_o[BL_ * DIM_];                      // [B,L,H,D] == [B,L,DIM]

// ----------------------------------------------------------------------------
// SGEMM: C[M,N] = A[M,K] @ B[K,N] (+ bias[N]), row-major, tiles 128x128x16
// ----------------------------------------------------------------------------
__global__ __launch_bounds__(256) void sgemm128(
    const float* __restrict__ A, const float* __restrict__ Bm,
    const float* __restrict__ bias, float* __restrict__ C,
    int M, int N, int K)
{
    __shared__ float As[16][128];   // [k][m]
    __shared__ float Bs[16][128];   // [k][n]

    const int tid = threadIdx.x;
    const int tx = tid & 15;
    const int ty = tid >> 4;
    const int row0 = blockIdx.y * 128;
    const int col0 = blockIdx.x * 128;

    float acc[8][8];
#pragma unroll
    for (int i = 0; i < 8; i++)
#pragma unroll
        for (int j = 0; j < 8; j++) acc[i][j] = 0.f;

    for (int k0 = 0; k0 < K; k0 += 16) {
        // Load A tile (128x16), store transposed
#pragma unroll
        for (int it = 0; it < 2; it++) {
            int idx = tid + it * 256;       // 0..511
            int r = idx >> 2;               // 0..127
            int kq = idx & 3;               // 0..3
            float4 a = *(const float4*)(A + (size_t)(row0 + r) * K + k0 + kq * 4);
            As[kq * 4 + 0][r] = a.x;
            As[kq * 4 + 1][r] = a.y;
            As[kq * 4 + 2][r] = a.z;
            As[kq * 4 + 3][r] = a.w;
        }
        // Load B tile (16x128)
#pragma unroll
        for (int it = 0; it < 2; it++) {
            int idx = tid + it * 256;
            int kr = idx >> 5;              // 0..15
            int cq = idx & 31;              // 0..31
            *(float4*)(&Bs[kr][cq * 4]) =
                *(const float4*)(Bm + (size_t)(k0 + kr) * N + col0 + cq * 4);
        }
        __syncthreads();

#pragma unroll
        for (int k = 0; k < 16; k++) {
            float a[8], b[8];
            *(float4*)(a)     = *(float4*)(&As[k][ty * 8]);
            *(float4*)(a + 4) = *(float4*)(&As[k][ty * 8 + 4]);
            *(float4*)(b)     = *(float4*)(&Bs[k][tx * 8]);
            *(float4*)(b + 4) = *(float4*)(&Bs[k][tx * 8 + 4]);
#pragma unroll
            for (int i = 0; i < 8; i++)
#pragma unroll
                for (int j = 0; j < 8; j++) acc[i][j] += a[i] * b[j];
        }
        __syncthreads();
    }

#pragma unroll
    for (int i = 0; i < 8; i++) {
        int r = row0 + ty * 8 + i;
#pragma unroll
        for (int j = 0; j < 8; j += 4) {
            int c = col0 + tx * 8 + j;
            float4 v;
            v.x = acc[i][j + 0];
            v.y = acc[i][j + 1];
            v.z = acc[i][j + 2];
            v.w = acc[i][j + 3];
            if (bias) {
                v.x += bias[c + 0];
                v.y += bias[c + 1];
                v.z += bias[c + 2];
                v.w += bias[c + 3];
            }
            *(float4*)(C + (size_t)r * N + c) = v;
        }
    }
}

// ----------------------------------------------------------------------------
// RMSNorm (over D=64) + RoPE; split qkv into q/k/v in [B,H,L,D].
// One warp per (b,h,l): lane handles d = 2*lane, 2*lane+1 (a RoPE pair).
// ----------------------------------------------------------------------------
__global__ __launch_bounds__(256) void rmsrope_kernel(
    const float* __restrict__ qkv, const float* __restrict__ pe,
    const float* __restrict__ qscale, const float* __restrict__ kscale,
    float* __restrict__ q, float* __restrict__ k, float* __restrict__ v)
{
    const int warp = (blockIdx.x * blockDim.x + threadIdx.x) >> 5;  // 0..65535
    const int lane = threadIdx.x & 31;
    const int b = warp >> 15;           // / (H*L)
    const int rem = warp & 32767;
    const int h = rem >> 11;            // / L
    const int l = rem & 2047;

    const float* base = qkv + ((size_t)(b * L_ + l)) * (3 * DIM_) + h * D_;
    float2 q2 = *(const float2*)(base + lane * 2);
    float2 k2 = *(const float2*)(base + DIM_ + lane * 2);
    float2 v2 = *(const float2*)(base + 2 * DIM_ + lane * 2);

    float sq = q2.x * q2.x + q2.y * q2.y;
    float sk = k2.x * k2.x + k2.y * k2.y;
#pragma unroll
    for (int o = 16; o > 0; o >>= 1) {
        sq += __shfl_xor_sync(0xffffffffu, sq, o);
        sk += __shfl_xor_sync(0xffffffffu, sk, o);
    }
    const float qinv = rsqrtf(sq * (1.f / 64.f) + 1e-6f);
    const float kinv = rsqrtf(sk * (1.f / 64.f) + 1e-6f);

    float2 qsc = *(const float2*)(qscale + lane * 2);
    float2 ksc = *(const float2*)(kscale + lane * 2);
    float t0 = q2.x * qinv * qsc.x;
    float t1 = q2.y * qinv * qsc.y;
    float u0 = k2.x * kinv * ksc.x;
    float u1 = k2.y * kinv * ksc.y;

    // pe[b,0,l,j,r,c]; j = lane
    float4 p = *(const float4*)(pe + (((size_t)(b * L_ + l)) * 32 + lane) * 4);
    float2 qo, ko;
    qo.x = p.x * t0 + p.y * t1;   // r=0
    qo.y = p.z * t0 + p.w * t1;   // r=1
    ko.x = p.x * u0 + p.y * u1;
    ko.y = p.z * u0 + p.w * u1;

    const size_t orow = ((size_t)((b * H_ + h) * L_ + l)) * D_;
    *(float2*)(q + orow + lane * 2) = qo;
    *(float2*)(k + orow + lane * 2) = ko;
    *(float2*)(v + orow + lane * 2) = v2;
}

// ----------------------------------------------------------------------------
// Flash attention fp32: 64x64 tiles. Q/K stored d-major in smem so both GEMM
// phases read float4. Online softmax by 64 row-threads on transposed S.
// Writes O directly in [B,L,H,D] layout for the projection GEMM.
// ----------------------------------------------------------------------------
#define APAD 68                       // padded row of 68 floats (16B-aligned)
#define ATTN_SMEM_BYTES ((4 * 64 * APAD + 3 * 64) * 4)

__global__ __launch_bounds__(256) void attn_kernel(
    const float* __restrict__ q, const float* __restrict__ k,
    const float* __restrict__ v, float* __restrict__ o)
{
    extern __shared__ float sm[];
    float* sQt = sm;                    // [d][r]
    float* sKt = sm + 64 * APAD;        // [d][c]
    float* sV  = sm + 2 * 64 * APAD;    // [c][d]
    float* sS  = sm + 3 * 64 * APAD;    // [c][r]  (transposed scores)
    float* rM  = sm + 4 * 64 * APAD;    // [64]
    float* rL  = rM + 64;
    float* rA  = rL + 64;

    const int tid = threadIdx.x;
    const int tx = tid & 15;
    const int ty = tid >> 4;
    const int bh = blockIdx.y;          // 0..31
    const int q0 = blockIdx.x * 64;
    const size_t bhoff = (size_t)bh * L_ * D_;
    const float* Q = q + bhoff;
    const float* K = k + bhoff;
    const float* V = v + bhoff;
    const float scale = 0.125f;         // 1/sqrt(64)

    // Load Q tile, scaled, transposed to [d][r]
#pragma unroll
    for (int it = 0; it < 4; it++) {
        int idx = tid + it * 256;
        int r = idx >> 4;
        int dq = idx & 15;
        float4 a = *(const float4*)(Q + (size_t)(q0 + r) * D_ + dq * 4);
        sQt[(dq * 4 + 0) * APAD + r] = a.x * scale;
        sQt[(dq * 4 + 1) * APAD + r] = a.y * scale;
        sQt[(dq * 4 + 2) * APAD + r] = a.z * scale;
        sQt[(dq * 4 + 3) * APAD + r] = a.w * scale;
    }
    if (tid < 64) { rM[tid] = -INFINITY; rL[tid] = 0.f; }

    float acc[4][4];
#pragma unroll
    for (int i = 0; i < 4; i++)
#pragma unroll
        for (int j = 0; j < 4; j++) acc[i][j] = 0.f;

    __syncthreads();

    for (int c0 = 0; c0 < L_; c0 += 64) {
        // Load K tile transposed, V tile direct
#pragma unroll
        for (int it = 0; it < 4; it++) {
            int idx = tid + it * 256;
            int r = idx >> 4;
            int dq = idx & 15;
            float4 a = *(const float4*)(K + (size_t)(c0 + r) * D_ + dq * 4);
            sKt[(dq * 4 + 0) * APAD + r] = a.x;
            sKt[(dq * 4 + 1) * APAD + r] = a.y;
            sKt[(dq * 4 + 2) * APAD + r] = a.z;
            sKt[(dq * 4 + 3) * APAD + r] = a.w;
            float4 bvec = *(const float4*)(V + (size_t)(c0 + r) * D_ + dq * 4);
            *(float4*)(&sV[r * APAD + dq * 4]) = bvec;
        }
        __syncthreads();

        // S = Q K^T  (4x4 per thread)
        float s[4][4];
#pragma unroll
        for (int i = 0; i < 4; i++)
#pragma unroll
            for (int j = 0; j < 4; j++) s[i][j] = 0.f;
#pragma unroll 8
        for (int d = 0; d < 64; d++) {
            float4 qa = *(float4*)(&sQt[d * APAD + ty * 4]);
            float4 kb = *(float4*)(&sKt[d * APAD + tx * 4]);
            float qv[4] = {qa.x, qa.y, qa.z, qa.w};
            float kv[4] = {kb.x, kb.y, kb.z, kb.w};
#pragma unroll
            for (int i = 0; i < 4; i++)
#pragma unroll
                for (int j = 0; j < 4; j++) s[i][j] += qv[i] * kv[j];
        }
        // Store transposed: sS[c][r]
#pragma unroll
        for (int j = 0; j < 4; j++)
#pragma unroll
            for (int i = 0; i < 4; i++)
                sS[(tx * 4 + j) * APAD + ty * 4 + i] = s[i][j];
        __syncthreads();

        // Online softmax: one thread per query row
        if (tid < 64) {
            const int r = tid;
            float mold = rM[r];
            float mt = mold;
#pragma unroll 8
            for (int c = 0; c < 64; c++) mt = fmaxf(mt, sS[c * APAD + r]);
            float alpha = __expf(mold - mt);
            float sum = 0.f;
#pragma unroll 8
            for (int c = 0; c < 64; c++) {
                float p = __expf(sS[c * APAD + r] - mt);
                sS[c * APAD + r] = p;
                sum += p;
            }
            rM[r] = mt;
            rL[r] = rL[r] * alpha + sum;
            rA[r] = alpha;
        }
        __syncthreads();

        // acc = acc*alpha + P @ V
        float al[4];
#pragma unroll
        for (int i = 0; i < 4; i++) al[i] = rA[ty * 4 + i];
#pragma unroll
        for (int i = 0; i < 4; i++)
#pragma unroll
            for (int j = 0; j < 4; j++) acc[i][j] *= al[i];
#pragma unroll 8
        for (int c = 0; c < 64; c++) {
            float4 pa = *(float4*)(&sS[c * APAD + ty * 4]);
            float4 vb = *(float4*)(&sV[c * APAD + tx * 4]);
            float pv[4] = {pa.x, pa.y, pa.z, pa.w};
            float vv[4] = {vb.x, vb.y, vb.z, vb.w};
#pragma unroll
            for (int i = 0; i < 4; i++)
#pragma unroll
                for (int j = 0; j < 4; j++) acc[i][j] += pv[i] * vv[j];
        }
        __syncthreads();
    }

    // Epilogue: normalize + write [B,L,H,D]
    const int b = bh >> 4;
    const int h = bh & 15;
    float linv[4];
#pragma unroll
    for (int i = 0; i < 4; i++) linv[i] = 1.f / rL[ty * 4 + i];
#pragma unroll
    for (int i = 0; i < 4; i++) {
        int token = q0 + ty * 4 + i;
        float4 ov;
        ov.x = acc[i][0] * linv[i];
        ov.y = acc[i][1] * linv[i];
        ov.z = acc[i][2] * linv[i];
        ov.w = acc[i][3] * linv[i];
        *(float4*)(o + (((size_t)(b * L_ + token)) * H_ + h) * D_ + tx * 4) = ov;
    }
}

// ----------------------------------------------------------------------------
// Launch
// ----------------------------------------------------------------------------
extern "C" void kernel_launch(void* const* d_in, const int* in_sizes, int n_in,
                              void* d_out, int out_size)
{
    const float* x      = (const float*)d_in[0];
    const float* pe     = (const float*)d_in[1];
    const float* w_qkv  = (const float*)d_in[2];
    const float* qscale = (const float*)d_in[3];
    const float* kscale = (const float*)d_in[4];
    const float* w_proj = (const float*)d_in[5];
    const float* b_proj = (const float*)d_in[6];
    float* out = (float*)d_out;

    float *p_qkv, *p_q, *p_k, *p_v, *p_o;
    cudaGetSymbolAddress((void**)&p_qkv, g_qkv);
    cudaGetSymbolAddress((void**)&p_q, g_q);
    cudaGetSymbolAddress((void**)&p_k, g_k);
    cudaGetSymbolAddress((void**)&p_v, g_v);
    cudaGetSymbolAddress((void**)&p_o, g_o);

    cudaFuncSetAttribute(attn_kernel, cudaFuncAttributeMaxDynamicSharedMemorySize,
                         ATTN_SMEM_BYTES);

    // 1. QKV GEMM: [4096,1024] @ [1024,3072]
    {
        dim3 grid(3 * DIM_ / 128, BL_ / 128);
        sgemm128<<<grid, 256>>>(x, w_qkv, nullptr, p_qkv, BL_, 3 * DIM_, DIM_);
    }
    // 2. RMSNorm + RoPE + split
    {
        int warps = B_ * H_ * L_;              // 65536
        rmsrope_kernel<<<warps * 32 / 256, 256>>>(p_qkv, pe, qscale, kscale,
                                                  p_q, p_k, p_v);
    }
    // 3. Attention
    {
        dim3 grid(L_ / 64, BH_);
        attn_kernel<<<grid, 256, ATTN_SMEM_BYTES>>>(p_q, p_k, p_v, p_o);
    }
    // 4. Output projection: [4096,1024] @ [1024,1024] + bias
    {
        dim3 grid(DIM_ / 128, BL_ / 128);
        sgemm128<<<grid, 256>>>(p_o, w_proj, b_proj, out, BL_, DIM_, DIM_);
    }
}

// round 4
// speedup vs baseline: 1.6557x; 1.6539x over previous
#include <cuda_runtime.h>
#include <math.h>
#include <stdint.h>

// ----------------------------------------------------------------------------
// Problem constants
// ----------------------------------------------------------------------------
#define B_   2
#define L_   2048
#define DIM_ 1024
#define H_   16
#define D_   64
#define BL_  (B_ * L_)         // 4096
#define BH_  (B_ * H_)         // 32

// Scratch (device globals — allocation-free per harness rules)
__device__ float g_qkv[BL_ * 3 * DIM_];                // [4096, 3072]
__device__ float g_q[BH_ * L_ * D_];                   // [B,H,L,D]
__device__ float g_k[BH_ * L_ * D_];
__device__ float g_v[BH_ * L_ * D_];
__device__ float g_o[BL_ * DIM_];                      // [B,L,H,D] == [B,L,DIM]

// ----------------------------------------------------------------------------
// SGEMM: C[M,N] = A[M,K] @ B[K,N] (+ bias[N]), row-major, tiles 128x128x16
// ----------------------------------------------------------------------------
__global__ __launch_bounds__(256) void sgemm128(
    const float* __restrict__ A, const float* __restrict__ Bm,
    const float* __restrict__ bias, float* __restrict__ C,
    int M, int N, int K)
{
    __shared__ float As[16][128];   // [k][m]
    __shared__ float Bs[16][128];   // [k][n]

    const int tid = threadIdx.x;
    const int tx = tid & 15;
    const int ty = tid >> 4;
    const int row0 = blockIdx.y * 128;
    const int col0 = blockIdx.x * 128;

    float acc[8][8];
#pragma unroll
    for (int i = 0; i < 8; i++)
#pragma unroll
        for (int j = 0; j < 8; j++) acc[i][j] = 0.f;

    for (int k0 = 0; k0 < K; k0 += 16) {
#pragma unroll
        for (int it = 0; it < 2; it++) {
            int idx = tid + it * 256;       // 0..511
            int r = idx >> 2;               // 0..127
            int kq = idx & 3;               // 0..3
            float4 a = *(const float4*)(A + (size_t)(row0 + r) * K + k0 + kq * 4);
            As[kq * 4 + 0][r] = a.x;
            As[kq * 4 + 1][r] = a.y;
            As[kq * 4 + 2][r] = a.z;
            As[kq * 4 + 3][r] = a.w;
        }
#pragma unroll
        for (int it = 0; it < 2; it++) {
            int idx = tid + it * 256;
            int kr = idx >> 5;              // 0..15
            int cq = idx & 31;              // 0..31
            *(float4*)(&Bs[kr][cq * 4]) =
                *(const float4*)(Bm + (size_t)(k0 + kr) * N + col0 + cq * 4);
        }
        __syncthreads();

#pragma unroll
        for (int k = 0; k < 16; k++) {
            float a[8], b[8];
            *(float4*)(a)     = *(float4*)(&As[k][ty * 8]);
            *(float4*)(a + 4) = *(float4*)(&As[k][ty * 8 + 4]);
            *(float4*)(b)     = *(float4*)(&Bs[k][tx * 8]);
            *(float4*)(b + 4) = *(float4*)(&Bs[k][tx * 8 + 4]);
#pragma unroll
            for (int i = 0; i < 8; i++)
#pragma unroll
                for (int j = 0; j < 8; j++) acc[i][j] += a[i] * b[j];
        }
        __syncthreads();
    }

#pragma unroll
    for (int i = 0; i < 8; i++) {
        int r = row0 + ty * 8 + i;
#pragma unroll
        for (int j = 0; j < 8; j += 4) {
            int c = col0 + tx * 8 + j;
            float4 v;
            v.x = acc[i][j + 0];
            v.y = acc[i][j + 1];
            v.z = acc[i][j + 2];
            v.w = acc[i][j + 3];
            if (bias) {
                v.x += bias[c + 0];
                v.y += bias[c + 1];
                v.z += bias[c + 2];
                v.w += bias[c + 3];
            }
            *(float4*)(C + (size_t)r * N + c) = v;
        }
    }
}

// ----------------------------------------------------------------------------
// RMSNorm (over D=64) + RoPE; split qkv into q/k/v in [B,H,L,D].
// ----------------------------------------------------------------------------
__global__ __launch_bounds__(256) void rmsrope_kernel(
    const float* __restrict__ qkv, const float* __restrict__ pe,
    const float* __restrict__ qscale, const float* __restrict__ kscale,
    float* __restrict__ q, float* __restrict__ k, float* __restrict__ v)
{
    const int warp = (blockIdx.x * blockDim.x + threadIdx.x) >> 5;  // 0..65535
    const int lane = threadIdx.x & 31;
    const int b = warp >> 15;
    const int rem = warp & 32767;
    const int h = rem >> 11;
    const int l = rem & 2047;

    const float* base = qkv + ((size_t)(b * L_ + l)) * (3 * DIM_) + h * D_;
    float2 q2 = *(const float2*)(base + lane * 2);
    float2 k2 = *(const float2*)(base + DIM_ + lane * 2);
    float2 v2 = *(const float2*)(base + 2 * DIM_ + lane * 2);

    float sq = q2.x * q2.x + q2.y * q2.y;
    float sk = k2.x * k2.x + k2.y * k2.y;
#pragma unroll
    for (int o = 16; o > 0; o >>= 1) {
        sq += __shfl_xor_sync(0xffffffffu, sq, o);
        sk += __shfl_xor_sync(0xffffffffu, sk, o);
    }
    const float qinv = rsqrtf(sq * (1.f / 64.f) + 1e-6f);
    const float kinv = rsqrtf(sk * (1.f / 64.f) + 1e-6f);

    float2 qsc = *(const float2*)(qscale + lane * 2);
    float2 ksc = *(const float2*)(kscale + lane * 2);
    float t0 = q2.x * qinv * qsc.x;
    float t1 = q2.y * qinv * qsc.y;
    float u0 = k2.x * kinv * ksc.x;
    float u1 = k2.y * kinv * ksc.y;

    float4 p = *(const float4*)(pe + (((size_t)(b * L_ + l)) * 32 + lane) * 4);
    float2 qo, ko;
    qo.x = p.x * t0 + p.y * t1;
    qo.y = p.z * t0 + p.w * t1;
    ko.x = p.x * u0 + p.y * u1;
    ko.y = p.z * u0 + p.w * u1;

    const size_t orow = ((size_t)((b * H_ + h) * L_ + l)) * D_;
    *(float2*)(q + orow + lane * 2) = qo;
    *(float2*)(k + orow + lane * 2) = ko;
    *(float2*)(v + orow + lane * 2) = v2;
}

// ----------------------------------------------------------------------------
// Flash attention with tf32 tensor-core MMA (mma.sync.m16n8k8).
// Block = 128 threads (4 warps). 64 queries/block; warp w owns query rows
// [16w, 16w+16). Iterates over key tiles of 64. Softmax fully in registers
// (each row lives in one 4-lane quad). P re-fragmented through per-warp smem.
// Output written directly in [B,L,H,D].
// ----------------------------------------------------------------------------
#define PAD 68
#define SK_OFF   0
#define SV_OFF   (64 * PAD)
#define SP_OFF   (2 * 64 * PAD)
#define ATTN_SMEM_FLOATS (3 * 64 * PAD)
#define ATTN_SMEM_BYTES  (ATTN_SMEM_FLOATS * 4)

__device__ __forceinline__ uint32_t f2tf32(float x) {
    uint32_t r;
    asm("cvt.rna.tf32.f32 %0, %1;" : "=r"(r) : "f"(x));
    return r;
}

__device__ __forceinline__ void mma_tf32(float* d, const uint32_t* a,
                                         uint32_t b0, uint32_t b1) {
    asm volatile(
        "mma.sync.aligned.m16n8k8.row.col.f32.tf32.tf32.f32 "
        "{%0,%1,%2,%3}, {%4,%5,%6,%7}, {%8,%9}, {%0,%1,%2,%3};\n"
        : "+f"(d[0]), "+f"(d[1]), "+f"(d[2]), "+f"(d[3])
        : "r"(a[0]), "r"(a[1]), "r"(a[2]), "r"(a[3]), "r"(b0), "r"(b1));
}

__global__ __launch_bounds__(128) void attn_mma(
    const float* __restrict__ q, const float* __restrict__ k,
    const float* __restrict__ v, float* __restrict__ o)
{
    extern __shared__ float sm[];
    float* sK = sm + SK_OFF;            // [64][PAD] tf32 bits
    float* sV = sm + SV_OFF;            // [64][PAD] tf32 bits
    float* sP = sm + SP_OFF;            // 4 warps x [16][PAD] tf32 bits

    const int tid  = threadIdx.x;
    const int lane = tid & 31;
    const int warp = tid >> 5;          // 0..3
    const int gid  = lane >> 2;         // 0..7
    const int tig  = lane & 3;          // 0..3
    const int bh = blockIdx.y;
    const int q0 = blockIdx.x * 64;
    const size_t bhoff = (size_t)bh * L_ * D_;
    const float* Q = q + bhoff;
    const float* K = k + bhoff;
    const float* V = v + bhoff;

    // scale folds 1/sqrt(D) and log2(e) so softmax uses exp2
    const float QSCALE = 0.125f * 1.4426950408889634f;

    // ---- Q fragments (A operand), held for whole block ----
    const int r0 = q0 + warp * 16 + gid;   // row of a0/a2
    uint32_t qf[8][4];
#pragma unroll
    for (int kk = 0; kk < 8; kk++) {
        qf[kk][0] = f2tf32(Q[(size_t)r0 * D_ + kk * 8 + tig] * QSCALE);
        qf[kk][1] = f2tf32(Q[(size_t)(r0 + 8) * D_ + kk * 8 + tig] * QSCALE);
        qf[kk][2] = f2tf32(Q[(size_t)r0 * D_ + kk * 8 + tig + 4] * QSCALE);
        qf[kk][3] = f2tf32(Q[(size_t)(r0 + 8) * D_ + kk * 8 + tig + 4] * QSCALE);
    }

    float of[8][4];
#pragma unroll
    for (int nt = 0; nt < 8; nt++)
#pragma unroll
        for (int j = 0; j < 4; j++) of[nt][j] = 0.f;

    float m0 = -INFINITY, m1 = -INFINITY;   // running max (rows gid, gid+8)
    float l0 = 0.f, l1 = 0.f;               // running sum (this lane's cols)

    uint32_t* sPw = (uint32_t*)(sP + warp * 16 * PAD);

    for (int c0 = 0; c0 < L_; c0 += 64) {
        // ---- load K,V tile -> smem as tf32 bits ----
#pragma unroll
        for (int it = 0; it < 8; it++) {
            int idx = tid + it * 128;       // 0..1023
            int r = idx >> 4;
            int c4 = idx & 15;
            float4 a = *(const float4*)(K + (size_t)(c0 + r) * D_ + c4 * 4);
            uint4 ua = {f2tf32(a.x), f2tf32(a.y), f2tf32(a.z), f2tf32(a.w)};
            *(uint4*)(&sK[r * PAD + c4 * 4]) = ua;
            float4 bv = *(const float4*)(V + (size_t)(c0 + r) * D_ + c4 * 4);
            uint4 ub = {f2tf32(bv.x), f2tf32(bv.y), f2tf32(bv.z), f2tf32(bv.w)};
            *(uint4*)(&sV[r * PAD + c4 * 4]) = ub;
        }
        __syncthreads();

        // ---- S = Q K^T  (warp's 16 rows x 64 cols) ----
        float sf[8][4];
#pragma unroll
        for (int nt = 0; nt < 8; nt++)
#pragma unroll
            for (int j = 0; j < 4; j++) sf[nt][j] = 0.f;

        const uint32_t* sKu = (const uint32_t*)sK;
#pragma unroll
        for (int kk = 0; kk < 8; kk++) {
#pragma unroll
            for (int nt = 0; nt < 8; nt++) {
                uint32_t b0 = sKu[(nt * 8 + gid) * PAD + kk * 8 + tig];
                uint32_t b1 = sKu[(nt * 8 + gid) * PAD + kk * 8 + tig + 4];
                mma_tf32(sf[nt], qf[kk], b0, b1);
            }
        }

        // ---- online softmax in registers ----
        float mn0 = m0, mn1 = m1;
#pragma unroll
        for (int nt = 0; nt < 8; nt++) {
            mn0 = fmaxf(mn0, fmaxf(sf[nt][0], sf[nt][1]));
            mn1 = fmaxf(mn1, fmaxf(sf[nt][2], sf[nt][3]));
        }
        mn0 = fmaxf(mn0, __shfl_xor_sync(0xffffffffu, mn0, 1));
        mn0 = fmaxf(mn0, __shfl_xor_sync(0xffffffffu, mn0, 2));
        mn1 = fmaxf(mn1, __shfl_xor_sync(0xffffffffu, mn1, 1));
        mn1 = fmaxf(mn1, __shfl_xor_sync(0xffffffffu, mn1, 2));
        float a0 = exp2f(m0 - mn0);
        float a1 = exp2f(m1 - mn1);
        m0 = mn0; m1 = mn1;
        l0 *= a0; l1 *= a1;

#pragma unroll
        for (int nt = 0; nt < 8; nt++) {
            float p00 = exp2f(sf[nt][0] - m0);
            float p01 = exp2f(sf[nt][1] - m0);
            float p10 = exp2f(sf[nt][2] - m1);
            float p11 = exp2f(sf[nt][3] - m1);
            l0 += p00 + p01;
            l1 += p10 + p11;
            uint2 u0 = {f2tf32(p00), f2tf32(p01)};
            uint2 u1 = {f2tf32(p10), f2tf32(p11)};
            *(uint2*)(&sPw[gid * PAD + nt * 8 + 2 * tig]) = u0;
            *(uint2*)(&sPw[(gid + 8) * PAD + nt * 8 + 2 * tig]) = u1;
            // rescale O accumulators
            of[nt][0] *= a0; of[nt][1] *= a0;
            of[nt][2] *= a1; of[nt][3] *= a1;
        }
        __syncwarp();

        // ---- O += P @ V ----
        const uint32_t* sVu = (const uint32_t*)sV;
#pragma unroll
        for (int kk = 0; kk < 8; kk++) {
            uint32_t af[4];
            af[0] = sPw[gid * PAD + kk * 8 + tig];
            af[1] = sPw[(gid + 8) * PAD + kk * 8 + tig];
            af[2] = sPw[gid * PAD + kk * 8 + tig + 4];
            af[3] = sPw[(gid + 8) * PAD + kk * 8 + tig + 4];
#pragma unroll
            for (int nt = 0; nt < 8; nt++) {
                uint32_t b0 = sVu[(kk * 8 + tig) * PAD + nt * 8 + gid];
                uint32_t b1 = sVu[(kk * 8 + tig + 4) * PAD + nt * 8 + gid];
                mma_tf32(of[nt], af, b0, b1);
            }
        }
        __syncthreads();
    }

    // ---- epilogue: finish l, normalize, write [B,L,H,D] ----
    l0 += __shfl_xor_sync(0xffffffffu, l0, 1);
    l0 += __shfl_xor_sync(0xffffffffu, l0, 2);
    l1 += __shfl_xor_sync(0xffffffffu, l1, 1);
    l1 += __shfl_xor_sync(0xffffffffu, l1, 2);
    const float inv0 = 1.f / l0;
    const float inv1 = 1.f / l1;

    const int b = bh >> 4;
    const int h = bh & 15;
    float* orow0 = o + (((size_t)(b * L_ + r0)) * H_ + h) * D_;
    float* orow1 = o + (((size_t)(b * L_ + r0 + 8)) * H_ + h) * D_;
#pragma unroll
    for (int nt = 0; nt < 8; nt++) {
        float2 v0 = {of[nt][0] * inv0, of[nt][1] * inv0};
        float2 v1 = {of[nt][2] * inv1, of[nt][3] * inv1};
        *(float2*)(orow0 + nt * 8 + 2 * tig) = v0;
        *(float2*)(orow1 + nt * 8 + 2 * tig) = v1;
    }
}

// ----------------------------------------------------------------------------
// Launch
// ----------------------------------------------------------------------------
extern "C" void kernel_launch(void* const* d_in, const int* in_sizes, int n_in,
                              void* d_out, int out_size)
{
    const float* x      = (const float*)d_in[0];
    const float* pe     = (const float*)d_in[1];
    const float* w_qkv  = (const float*)d_in[2];
    const float* qscale = (const float*)d_in[3];
    const float* kscale = (const float*)d_in[4];
    const float* w_proj = (const float*)d_in[5];
    const float* b_proj = (const float*)d_in[6];
    float* out = (float*)d_out;

    float *p_qkv, *p_q, *p_k, *p_v, *p_o;
    cudaGetSymbolAddress((void**)&p_qkv, g_qkv);
    cudaGetSymbolAddress((void**)&p_q, g_q);
    cudaGetSymbolAddress((void**)&p_k, g_k);
    cudaGetSymbolAddress((void**)&p_v, g_v);
    cudaGetSymbolAddress((void**)&p_o, g_o);

    cudaFuncSetAttribute(attn_mma, cudaFuncAttributeMaxDynamicSharedMemorySize,
                         ATTN_SMEM_BYTES);

    // 1. QKV GEMM: [4096,1024] @ [1024,3072]
    {
        dim3 grid(3 * DIM_ / 128, BL_ / 128);
        sgemm128<<<grid, 256>>>(x, w_qkv, nullptr, p_qkv, BL_, 3 * DIM_, DIM_);
    }
    // 2. RMSNorm + RoPE + split
    {
        int warps = B_ * H_ * L_;              // 65536
        rmsrope_kernel<<<warps * 32 / 256, 256>>>(p_qkv, pe, qscale, kscale,
                                                  p_q, p_k, p_v);
    }
    // 3. Attention (tf32 tensor cores)
    {
        dim3 grid(L_ / 64, BH_);
        attn_mma<<<grid, 128, ATTN_SMEM_BYTES>>>(p_q, p_k, p_v, p_o);
    }
    // 4. Output projection: [4096,1024] @ [1024,1024] + bias
    {
        dim3 grid(DIM_ / 128, BL_ / 128);
        sgemm128<<<grid, 256>>>(p_o, w_proj, b_proj, out, BL_, DIM_, DIM_);
    }
}